// round 7
// baseline (speedup 1.0000x reference)
#include <cuda_runtime.h>

// StructuralLoss: fused local-xcorr loss, w=2 (4x4 windows, offsets -1..+2, zero-pad).
// Single launch; warp-strip register-rolling stencil; interior/edge specialization.

#define NN 4096
#define OUTW 58                 // output columns per warp (64-wide strip minus 6 halo)
#define CHUNK 64                // output rows per warp task
#define NSTRIPS 71              // ceil(4096/58)
#define NCHUNKS (NN / CHUNK)    // 64
#define NTASKS (NSTRIPS * NCHUNKS)   // 4544 = 568 * 8 (exact)
#define WPB 8
#define TPB (WPB * 32)
#define NBLOCKS (NTASKS / WPB)  // 568

__device__ double g_sum;        // zero at module load; reset by last block each run
__device__ unsigned g_count;    // wraps to 0 via atomicInc

__device__ __forceinline__ float2 hsum4(float2 a) {
    const unsigned FULL = 0xffffffffu;
    float ly = __shfl_up_sync(FULL, a.y, 1);
    float rx = __shfl_down_sync(FULL, a.x, 1);
    float ry = __shfl_down_sync(FULL, a.y, 1);
    float t = a.x + a.y + rx;
    float2 s;
    s.x = ly + t;   // a[m-1]+a[m]+a[m+1]+a[m+2]
    s.y = t + ry;
    return s;
}

__device__ __forceinline__ float lterm(float sii, float sjj, float sij) {
    sii = fmaxf(sii, 1e-20f);
    sjj = fmaxf(sjj, 1e-20f);
    float prod = fmaxf(sii * sjj, 1e-30f);   // keep rsqrt out of FTZ range
    float L = sij * rsqrtf(prod);            // |L| <= ~1 by Cauchy-Schwarz
    return fmaxf(L, -1.0f);
}

// One warp-task. INTERIOR=true: all loads in-bounds, no c-padding needed
// (strips 1..69, chunks 1..62); compiles to unpredicated LDG.64 and no SELs.
template <bool INTERIOR>
__device__ __forceinline__ float xcorr_task(const float* __restrict__ img1,
                                            const float* __restrict__ img2,
                                            int strip, int chunk, int lane) {
    const int i0 = chunk * CHUNK;
    const int cstart = strip * OUTW - 2;     // strip covers img cols [cstart, cstart+63]
    const int col0 = cstart + 2 * lane;      // lane's two columns (col0 even)
    const bool colok = INTERIOR || ((col0 >= 0) && (col0 < NN));
    const bool outok = (lane >= 1) && (lane <= 29) && (INTERIOR || (col0 < NN));

    const float* b1 = img1 + col0;
    const float* b2 = img2 + col0;

    auto ldrow = [&](const float* __restrict__ b, int r) -> float2 {
        if (INTERIOR) {
            return *reinterpret_cast<const float2*>(b + (long long)r * NN);
        }
        if (colok && ((unsigned)r < (unsigned)NN)) {
            return *reinterpret_cast<const float2*>(b + (long long)r * NN);
        }
        return make_float2(0.f, 0.f);
    };

    const float2 z = make_float2(0.f, 0.f);
    float2 x1R[4], x2R[4], h1R[4], h2R[4];
    float2 PiiR[4], PjjR[4], PijR[4];
#pragma unroll
    for (int k = 0; k < 4; ++k) {
        x1R[k] = z; x2R[k] = z; h1R[k] = z; h2R[k] = z;
        PiiR[k] = z; PjjR[k] = z; PijR[k] = z;
    }
    float2 V1 = z, V2 = z, Sii = z, Sjj = z, Sij = z;
    float acc = 0.f;

    // Pipeline: at iteration i we consume img row i+4, produce c row i+2,
    // and emit output row i. 6 warm-up iterations flush zero-initialized rings.
    const int istart = i0 - 6;
    float2 pf1 = ldrow(b1, istart + 4);
    float2 pf2 = ldrow(b2, istart + 4);

#pragma unroll 1
    for (int ib = 0; ib < 72; ib += 4) {   // 6 warmup + 64 output + 2 drain
#pragma unroll
        for (int u = 0; u < 4; ++u) {
            const int i = istart + ib + u;
            const int ks = (u + 2) & 3;    // == i & 3     (istart % 4 == 2)
            const int kr = u;              // == (i+2) & 3

            // consume prefetched row i+4, prefetch row i+5
            float2 a1 = pf1, a2 = pf2;
            x1R[ks] = a1; x2R[ks] = a2;
            // last prefetch touches row istart+72+4+1 = i0+71; interior chunks
            // (chunk<=62 -> i0<=3968) keep this < 4096, so unpredicated is safe.
            pf1 = ldrow(b1, i + 5);
            pf2 = ldrow(b2, i + 5);

            // horizontal 4-sum of new img row; rolling vertical sum (rows i+1..i+4)
            float2 h1 = hsum4(a1);
            float2 h2 = hsum4(a2);
            V1.x += h1.x - h1R[ks].x; V1.y += h1.y - h1R[ks].y;
            V2.x += h2.x - h2R[ks].x; V2.y += h2.y - h2R[ks].y;
            h1R[ks] = h1; h2R[ks] = h2;

            // centered values at row i+2 (zero outside the image = c1/c2 padding)
            float2 xa = x1R[kr], xb = x2R[kr];
            float2 c1, c2;
            if (INTERIOR) {
                c1.x = xa.x - V1.x * 0.0625f;  c1.y = xa.y - V1.y * 0.0625f;
                c2.x = xb.x - V2.x * 0.0625f;  c2.y = xb.y - V2.y * 0.0625f;
            } else {
                bool cv = colok && ((unsigned)(i + 2) < (unsigned)NN);
                c1.x = cv ? (xa.x - V1.x * 0.0625f) : 0.f;
                c1.y = cv ? (xa.y - V1.y * 0.0625f) : 0.f;
                c2.x = cv ? (xb.x - V2.x * 0.0625f) : 0.f;
                c2.y = cv ? (xb.y - V2.y * 0.0625f) : 0.f;
            }

            // products, horizontal 4-sums, rolling vertical 4-sums (rows i-1..i+2)
            float2 pii, pjj, pij;
            pii.x = c1.x * c1.x; pii.y = c1.y * c1.y;
            pjj.x = c2.x * c2.x; pjj.y = c2.y * c2.y;
            pij.x = c1.x * c2.x; pij.y = c1.y * c2.y;

            float2 Pii = hsum4(pii);
            float2 Pjj = hsum4(pjj);
            float2 Pij = hsum4(pij);

            Sii.x += Pii.x - PiiR[kr].x; Sii.y += Pii.y - PiiR[kr].y; PiiR[kr] = Pii;
            Sjj.x += Pjj.x - PjjR[kr].x; Sjj.y += Pjj.y - PjjR[kr].y; PjjR[kr] = Pjj;
            Sij.x += Pij.x - PijR[kr].x; Sij.y += Pij.y - PijR[kr].y; PijR[kr] = Pij;

            // emit output row i
            if (((unsigned)(i - i0) < (unsigned)CHUNK) && outok) {
                acc += lterm(Sii.x, Sjj.x, Sij.x);
                acc += lterm(Sii.y, Sjj.y, Sij.y);
            }
        }
    }
    return acc;
}

__global__ void __launch_bounds__(TPB, 2)
xcorr_kernel(const float* __restrict__ img1, const float* __restrict__ img2,
             float* __restrict__ out) {
    const int task = blockIdx.x * WPB + (threadIdx.x >> 5);   // < NTASKS (exact division)
    const int lane = threadIdx.x & 31;
    const int strip = task % NSTRIPS;
    const int chunk = task / NSTRIPS;

    const bool interior = (strip >= 1) && (strip <= NSTRIPS - 2) &&
                          (chunk >= 1) && (chunk <= NCHUNKS - 2);

    float acc;
    if (interior) acc = xcorr_task<true >(img1, img2, strip, chunk, lane);
    else          acc = xcorr_task<false>(img1, img2, strip, chunk, lane);

    // reduce: per-thread float partial (<=128 terms, |L|<=1) -> double warp sum -> atomic
    double v = (double)acc;
#pragma unroll
    for (int o = 16; o; o >>= 1) v += __shfl_xor_sync(0xffffffffu, v, o);
    if (lane == 0) atomicAdd(&g_sum, v);

    // last-block finalize
    __syncthreads();
    if (threadIdx.x == 0) {
        __threadfence();
        unsigned t = atomicInc(&g_count, NBLOCKS - 1);      // wraps to 0 after last block
        if (t == NBLOCKS - 1) {
            __threadfence();
            double total = atomicAdd(&g_sum, 0.0);
            float m = (float)(1.0 - total / ((double)NN * (double)NN));
            out[0] = m;
            out[1] = m;
            g_sum = 0.0;                                    // reset for next graph replay
            __threadfence();
        }
    }
}

extern "C" void kernel_launch(void* const* d_in, const int* in_sizes, int n_in,
                              void* d_out, int out_size) {
    const float* a = (const float*)d_in[0];   // outputs
    const float* b = (const float*)d_in[1];   // labels
    (void)in_sizes; (void)n_in; (void)out_size;
    xcorr_kernel<<<NBLOCKS, TPB>>>(a, b, (float*)d_out);
}

// round 11
// speedup vs baseline: 1.1383x; 1.1383x over previous
#include <cuda_runtime.h>

// StructuralLoss: fused local-xcorr loss, w=2 (4x4 windows, offsets -1..+2, zero-pad).
// Single launch; warp-strip register-rolling stencil; occupancy-optimized:
// depth-2 x-ring, fresh ring sums (no rolling accumulators), 3 CTAs/SM.

#define NN 4096
#define OUTW 58                 // output columns per warp (64-wide strip minus 6 halo)
#define CHUNK 32                // output rows per warp task
#define NSTRIPS 71              // ceil(4096/58)
#define NCHUNKS (NN / CHUNK)    // 128
#define NTASKS (NSTRIPS * NCHUNKS)   // 9088 = 1136 * 8 (exact)
#define WPB 8
#define TPB (WPB * 32)
#define NBLOCKS (NTASKS / WPB)  // 1136

__device__ double g_sum;        // zero at module load; reset by last block each run
__device__ unsigned g_count;    // wraps to 0 via atomicInc

__device__ __forceinline__ float2 hsum4(float2 a) {
    const unsigned FULL = 0xffffffffu;
    float ly = __shfl_up_sync(FULL, a.y, 1);
    float rx = __shfl_down_sync(FULL, a.x, 1);
    float ry = __shfl_down_sync(FULL, a.y, 1);
    float t = a.x + a.y + rx;
    float2 s;
    s.x = ly + t;   // a[m-1]+a[m]+a[m+1]+a[m+2]
    s.y = t + ry;
    return s;
}

__device__ __forceinline__ float2 ldrow(const float* __restrict__ b, int r, bool colok) {
    if (colok && ((unsigned)r < (unsigned)NN)) {
        return *reinterpret_cast<const float2*>(b + (long long)r * NN);
    }
    return make_float2(0.f, 0.f);
}

__device__ __forceinline__ float lterm(float sii, float sjj, float sij) {
    sii = fmaxf(sii, 1e-20f);
    sjj = fmaxf(sjj, 1e-20f);
    float prod = fmaxf(sii * sjj, 1e-30f);   // keep rsqrt out of FTZ range
    float L = sij * rsqrtf(prod);            // |L| <= ~1 by Cauchy-Schwarz
    return fmaxf(L, -1.0f);
}

__global__ void __launch_bounds__(TPB, 3)
xcorr_kernel(const float* __restrict__ img1, const float* __restrict__ img2,
             float* __restrict__ out) {
    const int task = blockIdx.x * WPB + (threadIdx.x >> 5);   // < NTASKS (exact division)
    const int lane = threadIdx.x & 31;
    const int strip = task % NSTRIPS;
    const int chunk = task / NSTRIPS;
    const int i0 = chunk * CHUNK;
    const int cstart = strip * OUTW - 2;     // strip covers img cols [cstart, cstart+63]
    const int col0 = cstart + 2 * lane;      // lane's two columns: col0, col0+1 (col0 even)
    const bool colok = (col0 >= 0) && (col0 < NN);
    const bool outok = (lane >= 1) && (lane <= 29) && (col0 < NN);

    const float* b1 = img1 + col0;
    const float* b2 = img2 + col0;

    const float2 z = make_float2(0.f, 0.f);
    float2 x1R[2], x2R[2];                    // raw rows, needed again 2 iters later
    float2 h1R[4], h2R[4];                    // h-row ring (V window = whole ring)
    float2 PiiR[4], PjjR[4], PijR[4];         // product-row ring (S window = whole ring)
#pragma unroll
    for (int k = 0; k < 2; ++k) { x1R[k] = z; x2R[k] = z; }
#pragma unroll
    for (int k = 0; k < 4; ++k) {
        h1R[k] = z; h2R[k] = z;
        PiiR[k] = z; PjjR[k] = z; PijR[k] = z;
    }
    float acc = 0.f;

    // Pipeline: at iteration i we consume img row i+4, produce c row i+2,
    // and emit output row i. 6 warm-up iterations fill the rings;
    // output row i only depends on img rows >= i-2.
    const int istart = i0 - 6;               // istart % 4 == 2 (i0 % 4 == 0)
    float2 pf1 = ldrow(b1, istart + 4, colok);
    float2 pf2 = ldrow(b2, istart + 4, colok);

#pragma unroll 1
    for (int ib = 0; ib < CHUNK + 8; ib += 4) {   // 6 warmup + CHUNK output + 2 drain
#pragma unroll
        for (int u = 0; u < 4; ++u) {
            const int i = istart + ib + u;
            const int ks = (u + 2) & 3;    // == i & 3      (h/P ring phase)
            const int kx = u & 1;          // == i & 1      (x ring phase, depth 2)

            // read x row i+2 (stored 2 iters ago in this slot), then consume
            // prefetched row i+4 into the same slot; prefetch row i+5
            float2 xa = x1R[kx], xb = x2R[kx];
            float2 a1 = pf1, a2 = pf2;
            x1R[kx] = a1; x2R[kx] = a2;
            pf1 = ldrow(b1, i + 5, colok);
            pf2 = ldrow(b2, i + 5, colok);

            // horizontal 4-sum of new img row into ring; V = fresh sum of ring
            h1R[ks] = hsum4(a1);
            h2R[ks] = hsum4(a2);
            float2 V1, V2;
            V1.x = (h1R[0].x + h1R[1].x) + (h1R[2].x + h1R[3].x);
            V1.y = (h1R[0].y + h1R[1].y) + (h1R[2].y + h1R[3].y);
            V2.x = (h2R[0].x + h2R[1].x) + (h2R[2].x + h2R[3].x);
            V2.y = (h2R[0].y + h2R[1].y) + (h2R[2].y + h2R[3].y);

            // centered values at row i+2 (zero outside the image = c1/c2 padding)
            bool cv = colok && ((unsigned)(i + 2) < (unsigned)NN);
            float2 c1, c2;
            c1.x = cv ? (xa.x - V1.x * 0.0625f) : 0.f;
            c1.y = cv ? (xa.y - V1.y * 0.0625f) : 0.f;
            c2.x = cv ? (xb.x - V2.x * 0.0625f) : 0.f;
            c2.y = cv ? (xb.y - V2.y * 0.0625f) : 0.f;

            // products, horizontal 4-sums into rings
            float2 pii, pjj, pij;
            pii.x = c1.x * c1.x; pii.y = c1.y * c1.y;
            pjj.x = c2.x * c2.x; pjj.y = c2.y * c2.y;
            pij.x = c1.x * c2.x; pij.y = c1.y * c2.y;

            PiiR[ks] = hsum4(pii);
            PjjR[ks] = hsum4(pjj);
            PijR[ks] = hsum4(pij);

            // emit output row i: S = fresh sum of product ring (rows i-1..i+2)
            if (((unsigned)(i - i0) < (unsigned)CHUNK) && outok) {
                float2 Sii, Sjj, Sij;
                Sii.x = (PiiR[0].x + PiiR[1].x) + (PiiR[2].x + PiiR[3].x);
                Sii.y = (PiiR[0].y + PiiR[1].y) + (PiiR[2].y + PiiR[3].y);
                Sjj.x = (PjjR[0].x + PjjR[1].x) + (PjjR[2].x + PjjR[3].x);
                Sjj.y = (PjjR[0].y + PjjR[1].y) + (PjjR[2].y + PjjR[3].y);
                Sij.x = (PijR[0].x + PijR[1].x) + (PijR[2].x + PijR[3].x);
                Sij.y = (PijR[0].y + PijR[1].y) + (PijR[2].y + PijR[3].y);
                acc += lterm(Sii.x, Sjj.x, Sij.x);
                acc += lterm(Sii.y, Sjj.y, Sij.y);
            }
        }
    }

    // reduce: per-thread float partial (<=64 terms, |L|<=1) -> double warp sum -> atomic
    double v = (double)acc;
#pragma unroll
    for (int o = 16; o; o >>= 1) v += __shfl_xor_sync(0xffffffffu, v, o);
    if (lane == 0) atomicAdd(&g_sum, v);

    // last-block finalize (single launch; graph = 1 node)
    __syncthreads();
    if (threadIdx.x == 0) {
        __threadfence();
        unsigned t = atomicInc(&g_count, NBLOCKS - 1);      // wraps to 0 after last block
        if (t == NBLOCKS - 1) {
            __threadfence();
            double total = atomicAdd(&g_sum, 0.0);
            float m = (float)(1.0 - total / ((double)NN * (double)NN));
            out[0] = m;
            out[1] = m;
            g_sum = 0.0;                                    // reset for next graph replay
            __threadfence();
        }
    }
}

extern "C" void kernel_launch(void* const* d_in, const int* in_sizes, int n_in,
                              void* d_out, int out_size) {
    const float* a = (const float*)d_in[0];   // outputs
    const float* b = (const float*)d_in[1];   // labels
    (void)in_sizes; (void)n_in; (void)out_size;
    xcorr_kernel<<<NBLOCKS, TPB>>>(a, b, (float*)d_out);
}

// round 13
// speedup vs baseline: 1.4672x; 1.2889x over previous
#include <cuda_runtime.h>

// StructuralLoss: fused local-xcorr loss, w=2 (4x4 windows, offsets -1..+2, zero-pad).
// Single launch; float4-per-lane warp-strip rolling stencil (128-col strips),
// depth-2 x-ring, fresh ring sums, 2 CTAs/SM.

#define NN 4096
#define OUTW 120                // output columns per warp strip (128 minus 8 halo)
#define CHUNK 32                // output rows per warp task
#define NSTRIPS 35              // ceil(4096/120)
#define NCHUNKS (NN / CHUNK)    // 128
#define NTASKS (NSTRIPS * NCHUNKS)   // 4480 = 560 * 8 (exact)
#define WPB 8
#define TPB (WPB * 32)
#define NBLOCKS (NTASKS / WPB)  // 560

__device__ double g_sum;        // reset by last block each run
__device__ unsigned g_count;    // wraps to 0 via atomicInc

// horizontal 4-tap sum (offsets -1..+2) for a lane holding 4 consecutive cols.
// 3 shuffles + 9 adds for 4 outputs.
__device__ __forceinline__ float4 hsum4q(float4 a) {
    const unsigned FULL = 0xffffffffu;
    float lw = __shfl_up_sync(FULL, a.w, 1);     // col0-1  (invalid for lane 0: halo only)
    float rx = __shfl_down_sync(FULL, a.x, 1);   // col0+4  (invalid for lane 31: halo only)
    float ry = __shfl_down_sync(FULL, a.y, 1);   // col0+5
    float t1 = a.y + a.z;
    float t2 = a.w + rx;
    float4 s;
    s.x = lw + a.x + t1;        // a[-1]+a[0]+a[1]+a[2]
    s.y = (a.x + a.w) + t1;     // a[0]+a[1]+a[2]+a[3]
    s.z = t1 + t2;              // a[1]+a[2]+a[3]+a[4]
    s.w = a.z + t2 + ry;        // a[2]+a[3]+a[4]+a[5]
    return s;
}

__device__ __forceinline__ float4 ldrow4(const float* __restrict__ b, int r, bool colok) {
    if (colok && ((unsigned)r < (unsigned)NN)) {
        return *reinterpret_cast<const float4*>(b + (long long)r * NN);
    }
    return make_float4(0.f, 0.f, 0.f, 0.f);
}

__device__ __forceinline__ float lterm(float sii, float sjj, float sij) {
    sii = fmaxf(sii, 1e-20f);
    sjj = fmaxf(sjj, 1e-20f);
    float prod = fmaxf(sii * sjj, 1e-30f);   // keep rsqrt out of FTZ range
    float L = sij * rsqrtf(prod);            // |L| <= ~1 by Cauchy-Schwarz
    return fmaxf(L, -1.0f);
}

__device__ __forceinline__ float4 sum4(const float4* R) {
    float4 s;
    s.x = (R[0].x + R[1].x) + (R[2].x + R[3].x);
    s.y = (R[0].y + R[1].y) + (R[2].y + R[3].y);
    s.z = (R[0].z + R[1].z) + (R[2].z + R[3].z);
    s.w = (R[0].w + R[1].w) + (R[2].w + R[3].w);
    return s;
}

__global__ void __launch_bounds__(TPB, 2)
xcorr_kernel(const float* __restrict__ img1, const float* __restrict__ img2,
             float* __restrict__ out) {
    const int task = blockIdx.x * WPB + (threadIdx.x >> 5);   // < NTASKS (exact division)
    const int lane = threadIdx.x & 31;
    const int strip = task % NSTRIPS;
    const int chunk = task / NSTRIPS;
    const int i0 = chunk * CHUNK;
    const int cstart = strip * OUTW - 4;     // strip covers img cols [cstart, cstart+127]
    const int col0 = cstart + 4 * lane;      // lane's 4 cols (col0 % 4 == 0 -> aligned f4)
    const bool colok = (col0 >= 0) && (col0 < NN);   // all 4 cols in/out together
    const bool outok = (lane >= 1) && (lane <= 30) && (col0 < NN);

    const float* b1 = img1 + col0;
    const float* b2 = img2 + col0;

    const float4 z = make_float4(0.f, 0.f, 0.f, 0.f);
    float4 x1R[2], x2R[2];                    // raw rows, reused 2 iters later
    float4 h1R[4], h2R[4];                    // h-row rings (V = ring sum)
    float4 PiiR[4], PjjR[4], PijR[4];         // product-row rings (S = ring sum)
#pragma unroll
    for (int k = 0; k < 2; ++k) { x1R[k] = z; x2R[k] = z; }
#pragma unroll
    for (int k = 0; k < 4; ++k) {
        h1R[k] = z; h2R[k] = z;
        PiiR[k] = z; PjjR[k] = z; PijR[k] = z;
    }
    float acc = 0.f;

    // Pipeline: at iteration i consume img row i+4, produce c row i+2, emit row i.
    const int istart = i0 - 6;               // istart % 4 == 2
    float4 pf1 = ldrow4(b1, istart + 4, colok);
    float4 pf2 = ldrow4(b2, istart + 4, colok);

#pragma unroll 1
    for (int ib = 0; ib < CHUNK + 8; ib += 4) {   // 6 warmup + CHUNK output + 2 drain
#pragma unroll
        for (int u = 0; u < 4; ++u) {
            const int i = istart + ib + u;
            const int ks = (u + 2) & 3;    // == i & 3      (h/P ring phase)
            const int kx = u & 1;          // == i & 1      (x ring phase)

            float4 xa = x1R[kx], xb = x2R[kx];   // row i+2 (stored 2 iters ago)
            float4 a1 = pf1, a2 = pf2;
            x1R[kx] = a1; x2R[kx] = a2;
            pf1 = ldrow4(b1, i + 5, colok);
            pf2 = ldrow4(b2, i + 5, colok);

            h1R[ks] = hsum4q(a1);
            h2R[ks] = hsum4q(a2);
            float4 V1 = sum4(h1R);
            float4 V2 = sum4(h2R);

            // centered values at row i+2 (zero outside the image)
            bool cv = colok && ((unsigned)(i + 2) < (unsigned)NN);
            float4 c1, c2;
            c1.x = cv ? (xa.x - V1.x * 0.0625f) : 0.f;
            c1.y = cv ? (xa.y - V1.y * 0.0625f) : 0.f;
            c1.z = cv ? (xa.z - V1.z * 0.0625f) : 0.f;
            c1.w = cv ? (xa.w - V1.w * 0.0625f) : 0.f;
            c2.x = cv ? (xb.x - V2.x * 0.0625f) : 0.f;
            c2.y = cv ? (xb.y - V2.y * 0.0625f) : 0.f;
            c2.z = cv ? (xb.z - V2.z * 0.0625f) : 0.f;
            c2.w = cv ? (xb.w - V2.w * 0.0625f) : 0.f;

            // products -> horizontal 4-sums -> rings (one type at a time)
            float4 p;
            p.x = c1.x * c1.x; p.y = c1.y * c1.y; p.z = c1.z * c1.z; p.w = c1.w * c1.w;
            PiiR[ks] = hsum4q(p);
            p.x = c2.x * c2.x; p.y = c2.y * c2.y; p.z = c2.z * c2.z; p.w = c2.w * c2.w;
            PjjR[ks] = hsum4q(p);
            p.x = c1.x * c2.x; p.y = c1.y * c2.y; p.z = c1.z * c2.z; p.w = c1.w * c2.w;
            PijR[ks] = hsum4q(p);

            // emit output row i: S = ring sums (rows i-1..i+2)
            if (((unsigned)(i - i0) < (unsigned)CHUNK) && outok) {
                float4 Sii = sum4(PiiR);
                float4 Sjj = sum4(PjjR);
                float4 Sij = sum4(PijR);
                acc += lterm(Sii.x, Sjj.x, Sij.x);
                acc += lterm(Sii.y, Sjj.y, Sij.y);
                acc += lterm(Sii.z, Sjj.z, Sij.z);
                acc += lterm(Sii.w, Sjj.w, Sij.w);
            }
        }
    }

    // reduce: per-thread float partial (<=128 terms, |L|<=1) -> double warp sum -> atomic
    double v = (double)acc;
#pragma unroll
    for (int o = 16; o; o >>= 1) v += __shfl_xor_sync(0xffffffffu, v, o);
    if (lane == 0) atomicAdd(&g_sum, v);

    // last-block finalize (single launch; graph = 1 node)
    __syncthreads();
    if (threadIdx.x == 0) {
        __threadfence();
        unsigned t = atomicInc(&g_count, NBLOCKS - 1);      // wraps to 0 after last block
        if (t == NBLOCKS - 1) {
            __threadfence();
            double total = atomicAdd(&g_sum, 0.0);
            float m = (float)(1.0 - total / ((double)NN * (double)NN));
            out[0] = m;
            out[1] = m;
            g_sum = 0.0;                                    // reset for next graph replay
            __threadfence();
        }
    }
}

extern "C" void kernel_launch(void* const* d_in, const int* in_sizes, int n_in,
                              void* d_out, int out_size) {
    const float* a = (const float*)d_in[0];   // outputs
    const float* b = (const float*)d_in[1];   // labels
    (void)in_sizes; (void)n_in; (void)out_size;
    xcorr_kernel<<<NBLOCKS, TPB>>>(a, b, (float*)d_out);
}

// round 14
// speedup vs baseline: 1.5548x; 1.0597x over previous
#include <cuda_runtime.h>

// StructuralLoss: fused local-xcorr loss, w=2 (4x4 windows, offsets -1..+2, zero-pad).
// Single launch; float4-per-lane warp-strip rolling stencil (128-col strips),
// depth-2 x-ring, fresh ring sums, 2 CTAs/SM, single-wave grid (280 blocks).

#define NN 4096
#define OUTW 120                // output columns per warp strip (128 minus 8 halo)
#define CHUNK 64                // output rows per warp task (single-wave grid)
#define NSTRIPS 35              // ceil(4096/120)
#define NCHUNKS (NN / CHUNK)    // 64
#define NTASKS (NSTRIPS * NCHUNKS)   // 2240 = 280 * 8 (exact)
#define WPB 8
#define TPB (WPB * 32)
#define NBLOCKS (NTASKS / WPB)  // 280  (< 304 CTA slots -> one wave)

__device__ double g_sum;        // reset by last block each run
__device__ unsigned g_count;    // wraps to 0 via atomicInc

// horizontal 4-tap sum (offsets -1..+2) for a lane holding 4 consecutive cols.
// 3 shuffles + 9 adds for 4 outputs.
__device__ __forceinline__ float4 hsum4q(float4 a) {
    const unsigned FULL = 0xffffffffu;
    float lw = __shfl_up_sync(FULL, a.w, 1);     // col0-1  (invalid for lane 0: halo only)
    float rx = __shfl_down_sync(FULL, a.x, 1);   // col0+4  (invalid for lane 31: halo only)
    float ry = __shfl_down_sync(FULL, a.y, 1);   // col0+5
    float t1 = a.y + a.z;
    float t2 = a.w + rx;
    float4 s;
    s.x = lw + a.x + t1;        // a[-1]+a[0]+a[1]+a[2]
    s.y = (a.x + a.w) + t1;     // a[0]+a[1]+a[2]+a[3]
    s.z = t1 + t2;              // a[1]+a[2]+a[3]+a[4]
    s.w = a.z + t2 + ry;        // a[2]+a[3]+a[4]+a[5]
    return s;
}

__device__ __forceinline__ float4 ldrow4(const float* __restrict__ b, int r, bool colok) {
    if (colok && ((unsigned)r < (unsigned)NN)) {
        return *reinterpret_cast<const float4*>(b + (long long)r * NN);
    }
    return make_float4(0.f, 0.f, 0.f, 0.f);
}

__device__ __forceinline__ float lterm(float sii, float sjj, float sij) {
    sii = fmaxf(sii, 1e-20f);
    sjj = fmaxf(sjj, 1e-20f);
    float prod = fmaxf(sii * sjj, 1e-30f);   // keep rsqrt out of FTZ range
    float L = sij * rsqrtf(prod);            // |L| <= ~1 by Cauchy-Schwarz
    return fmaxf(L, -1.0f);
}

__device__ __forceinline__ float4 sum4(const float4* R) {
    float4 s;
    s.x = (R[0].x + R[1].x) + (R[2].x + R[3].x);
    s.y = (R[0].y + R[1].y) + (R[2].y + R[3].y);
    s.z = (R[0].z + R[1].z) + (R[2].z + R[3].z);
    s.w = (R[0].w + R[1].w) + (R[2].w + R[3].w);
    return s;
}

__global__ void __launch_bounds__(TPB, 2)
xcorr_kernel(const float* __restrict__ img1, const float* __restrict__ img2,
             float* __restrict__ out) {
    const int task = blockIdx.x * WPB + (threadIdx.x >> 5);   // < NTASKS (exact division)
    const int lane = threadIdx.x & 31;
    const int strip = task % NSTRIPS;
    const int chunk = task / NSTRIPS;
    const int i0 = chunk * CHUNK;
    const int cstart = strip * OUTW - 4;     // strip covers img cols [cstart, cstart+127]
    const int col0 = cstart + 4 * lane;      // lane's 4 cols (col0 % 4 == 0 -> aligned f4)
    const bool colok = (col0 >= 0) && (col0 < NN);   // all 4 cols in/out together
    const bool outok = (lane >= 1) && (lane <= 30) && (col0 < NN);

    const float* b1 = img1 + col0;
    const float* b2 = img2 + col0;

    const float4 z = make_float4(0.f, 0.f, 0.f, 0.f);
    float4 x1R[2], x2R[2];                    // raw rows, reused 2 iters later
    float4 h1R[4], h2R[4];                    // h-row rings (V = ring sum)
    float4 PiiR[4], PjjR[4], PijR[4];         // product-row rings (S = ring sum)
#pragma unroll
    for (int k = 0; k < 2; ++k) { x1R[k] = z; x2R[k] = z; }
#pragma unroll
    for (int k = 0; k < 4; ++k) {
        h1R[k] = z; h2R[k] = z;
        PiiR[k] = z; PjjR[k] = z; PijR[k] = z;
    }
    float acc = 0.f;

    // Pipeline: at iteration i consume img row i+4, produce c row i+2, emit row i.
    const int istart = i0 - 6;               // istart % 4 == 2
    float4 pf1 = ldrow4(b1, istart + 4, colok);
    float4 pf2 = ldrow4(b2, istart + 4, colok);

#pragma unroll 1
    for (int ib = 0; ib < CHUNK + 8; ib += 4) {   // 6 warmup + CHUNK output + 2 drain
#pragma unroll
        for (int u = 0; u < 4; ++u) {
            const int i = istart + ib + u;
            const int ks = (u + 2) & 3;    // == i & 3      (h/P ring phase)
            const int kx = u & 1;          // == i & 1      (x ring phase)

            float4 xa = x1R[kx], xb = x2R[kx];   // row i+2 (stored 2 iters ago)
            float4 a1 = pf1, a2 = pf2;
            x1R[kx] = a1; x2R[kx] = a2;
            pf1 = ldrow4(b1, i + 5, colok);
            pf2 = ldrow4(b2, i + 5, colok);

            h1R[ks] = hsum4q(a1);
            h2R[ks] = hsum4q(a2);
            float4 V1 = sum4(h1R);
            float4 V2 = sum4(h2R);

            // centered values at row i+2 (zero outside the image)
            bool cv = colok && ((unsigned)(i + 2) < (unsigned)NN);
            float4 c1, c2;
            c1.x = cv ? (xa.x - V1.x * 0.0625f) : 0.f;
            c1.y = cv ? (xa.y - V1.y * 0.0625f) : 0.f;
            c1.z = cv ? (xa.z - V1.z * 0.0625f) : 0.f;
            c1.w = cv ? (xa.w - V1.w * 0.0625f) : 0.f;
            c2.x = cv ? (xb.x - V2.x * 0.0625f) : 0.f;
            c2.y = cv ? (xb.y - V2.y * 0.0625f) : 0.f;
            c2.z = cv ? (xb.z - V2.z * 0.0625f) : 0.f;
            c2.w = cv ? (xb.w - V2.w * 0.0625f) : 0.f;

            // products -> horizontal 4-sums -> rings (one type at a time)
            float4 p;
            p.x = c1.x * c1.x; p.y = c1.y * c1.y; p.z = c1.z * c1.z; p.w = c1.w * c1.w;
            PiiR[ks] = hsum4q(p);
            p.x = c2.x * c2.x; p.y = c2.y * c2.y; p.z = c2.z * c2.z; p.w = c2.w * c2.w;
            PjjR[ks] = hsum4q(p);
            p.x = c1.x * c2.x; p.y = c1.y * c2.y; p.z = c1.z * c2.z; p.w = c1.w * c2.w;
            PijR[ks] = hsum4q(p);

            // emit output row i: S = ring sums (rows i-1..i+2)
            if (((unsigned)(i - i0) < (unsigned)CHUNK) && outok) {
                float4 Sii = sum4(PiiR);
                float4 Sjj = sum4(PjjR);
                float4 Sij = sum4(PijR);
                acc += lterm(Sii.x, Sjj.x, Sij.x);
                acc += lterm(Sii.y, Sjj.y, Sij.y);
                acc += lterm(Sii.z, Sjj.z, Sij.z);
                acc += lterm(Sii.w, Sjj.w, Sij.w);
            }
        }
    }

    // reduce: per-thread float partial (<=256 terms, |L|<=1) -> double warp sum -> atomic
    double v = (double)acc;
#pragma unroll
    for (int o = 16; o; o >>= 1) v += __shfl_xor_sync(0xffffffffu, v, o);
    if (lane == 0) atomicAdd(&g_sum, v);

    // last-block finalize (single launch; graph = 1 node)
    __syncthreads();
    if (threadIdx.x == 0) {
        __threadfence();
        unsigned t = atomicInc(&g_count, NBLOCKS - 1);      // wraps to 0 after last block
        if (t == NBLOCKS - 1) {
            __threadfence();
            double total = atomicAdd(&g_sum, 0.0);
            float m = (float)(1.0 - total / ((double)NN * (double)NN));
            out[0] = m;
            out[1] = m;
            g_sum = 0.0;                                    // reset for next graph replay
            __threadfence();
        }
    }
}

extern "C" void kernel_launch(void* const* d_in, const int* in_sizes, int n_in,
                              void* d_out, int out_size) {
    const float* a = (const float*)d_in[0];   // outputs
    const float* b = (const float*)d_in[1];   // labels
    (void)in_sizes; (void)n_in; (void)out_size;
    xcorr_kernel<<<NBLOCKS, TPB>>>(a, b, (float*)d_out);
}